// round 9
// baseline (speedup 1.0000x reference)
#include <cuda_runtime.h>

#define NPRIMES 168
#define TPB 128
#define COLS 128
#define NT   4096          // column tiles = N / COLS
#define GBLK 1184          // gather-worker blocks (≈ one resident slot each)
#define TABN (NPRIMES * 1000)

// Interleaved (kernel, bias) table: one LDG.64 fetches both values.
__device__ float2 g_tab[TABN];
// Per-column (w, b), produced by gather workers, consumed by streamers.
__device__ float2 g_wb[NT * COLS];
// Per-tile ready flags. Zero-init at module load; consumer resets after use
// so every graph replay starts from 0.
__device__ int g_flag[NT];

// Per-prime magic-mod descriptor (compile-time, constant memory):
//  magic = floor(2^32/p)+1  ->  k % p == k - p*umulhi(k, magic)   (k < 2^20)
struct PInfo { unsigned magic; int p; };

#define PRIME_LIST \
 X(2) X(3) X(5) X(7) X(11) X(13) X(17) X(19) X(23) X(29) \
 X(31) X(37) X(41) X(43) X(47) X(53) X(59) X(61) X(67) X(71) \
 X(73) X(79) X(83) X(89) X(97) X(101) X(103) X(107) X(109) X(113) \
 X(127) X(131) X(137) X(139) X(149) X(151) X(157) X(163) X(167) X(173) \
 X(179) X(181) X(191) X(193) X(197) X(199) X(211) X(223) X(227) X(229) \
 X(233) X(239) X(241) X(251) X(257) X(263) X(269) X(271) X(277) X(281) \
 X(283) X(293) X(307) X(311) X(313) X(317) X(331) X(337) X(347) X(349) \
 X(353) X(359) X(367) X(373) X(379) X(383) X(389) X(397) X(401) X(409) \
 X(419) X(421) X(431) X(433) X(439) X(443) X(449) X(457) X(461) X(463) \
 X(467) X(479) X(487) X(491) X(499) X(503) X(509) X(521) X(523) X(541) \
 X(547) X(557) X(563) X(569) X(571) X(577) X(587) X(593) X(599) X(601) \
 X(607) X(613) X(617) X(619) X(631) X(641) X(643) X(647) X(653) X(659) \
 X(661) X(673) X(677) X(683) X(691) X(701) X(709) X(719) X(727) X(733) \
 X(739) X(743) X(751) X(757) X(761) X(769) X(773) X(787) X(797) X(809) \
 X(811) X(821) X(823) X(827) X(829) X(839) X(853) X(857) X(859) X(863) \
 X(877) X(881) X(883) X(887) X(907) X(911) X(919) X(929) X(937) X(941) \
 X(947) X(953) X(967) X(971) X(977) X(983) X(991) X(997)

__constant__ PInfo C_PI[NPRIMES] = {
#define X(p) { 0xFFFFFFFFu / (unsigned)(p) + 1u, (p) },
  PRIME_LIST
#undef X
};

__global__ __launch_bounds__(256)
void interleave_tab(const float* __restrict__ kern, const float* __restrict__ bias)
{
    int i = blockIdx.x * 256 + threadIdx.x;
    if (i < TABN) g_tab[i] = make_float2(kern[i], bias[i]);
}

// Gather one tile's 128 (w,b) pairs into g_wb and publish its flag.
__device__ __forceinline__ void gather_tile(int tile, int t)
{
    const unsigned k = (unsigned)(tile * COLS + t);
    float w = 0.f, a = 0.f;
    const float2* __restrict__ row = g_tab;

#pragma unroll 8
    for (int i = 0; i < NPRIMES; ++i) {
        const PInfo pi = C_PI[i];
        int m = (int)(k - (unsigned)pi.p * __umulhi(k, pi.magic));  // k % p
        float2 e = __ldg(row + m);
        w += e.x; a += e.y;
        row += 1000;
    }
    g_wb[k] = make_float2(w, a);

    __syncthreads();                    // all 128 wb stores issued before flag
    if (t == 0) {
        __threadfence();                // make wb visible at gpu scope
        asm volatile("st.global.release.gpu.b32 [%0], %1;"
                     :: "l"(g_flag + tile), "r"(1) : "memory");
    }
}

__global__ __launch_bounds__(TPB, 16)
void bwl_prime_main(const float* __restrict__ x,
                    float* __restrict__ out,
                    int N, int B)
{
    const int t   = threadIdx.x;
    const int bid = blockIdx.x;

    // ---- Gather duty (blocks 0..GBLK-1): other tiles first, own tile last,
    //      so resident wave-1 streamers (bid >= GBLK) unblock early. ----
    if (bid < GBLK) {
        for (int tile = bid + GBLK; tile < NT; tile += GBLK)
            gather_tile(tile, t);
        gather_tile(bid, t);
    }

    // ---- Stream duty (every block): tile `bid` ----
    const int tile = bid;
    const int k0   = tile * COLS;

    if (t == 0) {
        int f;
        for (;;) {
            asm volatile("ld.global.acquire.gpu.b32 %0, [%1];"
                         : "=r"(f) : "l"(g_flag + tile) : "memory");
            if (f) break;
            __nanosleep(64);
        }
    }
    __syncthreads();                    // broadcast readiness to block
    if (t == 0) g_flag[tile] = 0;       // reset for next graph replay

    // per-thread (w,b) for its 4 columns: 4 float2 = 2 coalesced float4 loads
    const int col4 = t & 31;
    const int rpg  = B >> 2;
    const int rbeg = (t >> 5) * rpg;

    const float4* wb4 = reinterpret_cast<const float4*>(g_wb + k0 + col4 * 4);
    const float4 p0 = __ldg(wb4);       // (w0,b0,w1,b1)
    const float4 p1 = __ldg(wb4 + 1);   // (w2,b2,w3,b3)
    const float4 wv = make_float4(p0.x, p0.z, p1.x, p1.z);
    const float4 bv = make_float4(p0.y, p0.w, p1.y, p1.w);

    const size_t nv = (size_t)(N >> 2);
    const float4* __restrict__ xv = reinterpret_cast<const float4*>(x)
                                    + (size_t)rbeg * nv + (k0 >> 2) + col4;
    float4* __restrict__       ov = reinterpret_cast<float4*>(out)
                                    + (size_t)rbeg * nv + (k0 >> 2) + col4;

#pragma unroll 8
    for (int r = 0; r < rpg; ++r) {
        float4 xi = __ldcs(xv);
        float4 o;
        o.x = fmaf(xi.x, wv.x, bv.x);
        o.y = fmaf(xi.y, wv.y, bv.y);
        o.z = fmaf(xi.z, wv.z, bv.z);
        o.w = fmaf(xi.w, wv.w, bv.w);
        __stcs(ov, o);
        xv += nv;
        ov += nv;
    }
}

extern "C" void kernel_launch(void* const* d_in, const int* in_sizes, int n_in,
                              void* d_out, int out_size)
{
    const float* x  = (const float*)d_in[0];   // (B, N) float32
    const float* kr = (const float*)d_in[1];   // (168, 1000) float32
    const float* br = (const float*)d_in[2];   // (168, 1000) float32
    float* out = (float*)d_out;

    const int N = 524288;
    const int B = in_sizes[0] / N;             // 64

    interleave_tab<<<(TABN + 255) / 256, 256>>>(kr, br);

    bwl_prime_main<<<NT, TPB>>>(x, out, N, B);
}

// round 10
// speedup vs baseline: 1.2826x; 1.2826x over previous
#include <cuda_runtime.h>

#define NPRIMES 168
#define TPB 256            // 128 producer threads + 128 consumer threads
#define COLS 128           // columns per tile
#define TILES 4            // tiles per block
#define TABN (NPRIMES * 1000)

// Interleaved (kernel, bias) table: one LDG.64 fetches both values.
__device__ float2 g_tab[TABN];

// Per-prime magic-mod descriptor (compile-time, constant memory):
//  magic = floor(2^32/p)+1  ->  k % p == k - p*umulhi(k, magic)   (k < 2^20)
struct PInfo { unsigned magic; int p; };

#define PRIME_LIST \
 X(2) X(3) X(5) X(7) X(11) X(13) X(17) X(19) X(23) X(29) \
 X(31) X(37) X(41) X(43) X(47) X(53) X(59) X(61) X(67) X(71) \
 X(73) X(79) X(83) X(89) X(97) X(101) X(103) X(107) X(109) X(113) \
 X(127) X(131) X(137) X(139) X(149) X(151) X(157) X(163) X(167) X(173) \
 X(179) X(181) X(191) X(193) X(197) X(199) X(211) X(223) X(227) X(229) \
 X(233) X(239) X(241) X(251) X(257) X(263) X(269) X(271) X(277) X(281) \
 X(283) X(293) X(307) X(311) X(313) X(317) X(331) X(337) X(347) X(349) \
 X(353) X(359) X(367) X(373) X(379) X(383) X(389) X(397) X(401) X(409) \
 X(419) X(421) X(431) X(433) X(439) X(443) X(449) X(457) X(461) X(463) \
 X(467) X(479) X(487) X(491) X(499) X(503) X(509) X(521) X(523) X(541) \
 X(547) X(557) X(563) X(569) X(571) X(577) X(587) X(593) X(599) X(601) \
 X(607) X(613) X(617) X(619) X(631) X(641) X(643) X(647) X(653) X(659) \
 X(661) X(673) X(677) X(683) X(691) X(701) X(709) X(719) X(727) X(733) \
 X(739) X(743) X(751) X(757) X(761) X(769) X(773) X(787) X(797) X(809) \
 X(811) X(821) X(823) X(827) X(829) X(839) X(853) X(857) X(859) X(863) \
 X(877) X(881) X(883) X(887) X(907) X(911) X(919) X(929) X(937) X(941) \
 X(947) X(953) X(967) X(971) X(977) X(983) X(991) X(997)

__constant__ PInfo C_PI[NPRIMES] = {
#define X(p) { 0xFFFFFFFFu / (unsigned)(p) + 1u, (p) },
  PRIME_LIST
#undef X
};

__global__ __launch_bounds__(256)
void interleave_tab(const float* __restrict__ kern, const float* __restrict__ bias)
{
    int i = blockIdx.x * 256 + threadIdx.x;
    if (i < TABN) g_tab[i] = make_float2(kern[i], bias[i]);
}

__global__ __launch_bounds__(TPB, 6)
void bwl_prime_main(const float* __restrict__ x,
                    float* __restrict__ out,
                    int N, int B)
{
    __shared__ float2 wb_s[TILES][COLS];   // (w,b) per column, per tile
    __shared__ int    flag[TILES];         // tile-ready flags (per-launch SMEM)

    const int t    = threadIdx.x;
    const int base = blockIdx.x * (COLS * TILES);
    const size_t nv = (size_t)(N >> 2);

    if (t < TILES) flag[t] = 0;
    __syncthreads();

    if (t < 128) {
        // ================= PRODUCER: warps 0-3 =================
        // Clean fat gather loop per tile (MLP preserved), then publish.
        for (int s = 0; s < TILES; ++s) {
            const unsigned k = (unsigned)(base + s * COLS + t);
            float w = 0.f, a = 0.f;
            const float2* __restrict__ row = g_tab;

#pragma unroll 8
            for (int i = 0; i < NPRIMES; ++i) {
                const PInfo pi = C_PI[i];
                int m = (int)(k - (unsigned)pi.p * __umulhi(k, pi.magic)); // k%p
                float2 e = __ldg(row + m);
                w += e.x; a += e.y;
                row += 1000;
            }
            wb_s[s][t] = make_float2(w, a);

            // producer-only barrier: all 128 wb stores drained & visible
            asm volatile("bar.sync 1, 128;" ::: "memory");
            if (t == 0) {
                unsigned fa = (unsigned)__cvta_generic_to_shared(&flag[s]);
                asm volatile("st.release.cta.shared.b32 [%0], %1;"
                             :: "r"(fa), "r"(1) : "memory");
            }
        }
        // producers retire; consumers keep the block alive
    } else {
        // ================= CONSUMER: warps 4-7 =================
        const int ct   = t - 128;
        const int col4 = ct & 31;               // float4 column within tile
        const int rpg  = B >> 2;                // 16 rows per group
        const int rbeg = (ct >> 5) * rpg;

        for (int s = 0; s < TILES; ++s) {
            // acquire-spin on tile flag (SMEM broadcast read)
            {
                unsigned fa = (unsigned)__cvta_generic_to_shared(&flag[s]);
                int f;
                for (;;) {
                    asm volatile("ld.acquire.cta.shared.b32 %0, [%1];"
                                 : "=r"(f) : "r"(fa) : "memory");
                    if (f) break;
                    __nanosleep(32);
                }
            }

            const float2 wb0 = wb_s[s][col4 * 4 + 0];
            const float2 wb1 = wb_s[s][col4 * 4 + 1];
            const float2 wb2 = wb_s[s][col4 * 4 + 2];
            const float2 wb3 = wb_s[s][col4 * 4 + 3];

            const int k0 = base + s * COLS;
            const float4* __restrict__ xv = reinterpret_cast<const float4*>(x)
                                            + (size_t)rbeg * nv + (k0 >> 2) + col4;
            float4* __restrict__       ov = reinterpret_cast<float4*>(out)
                                            + (size_t)rbeg * nv + (k0 >> 2) + col4;

#pragma unroll 8
            for (int r = 0; r < rpg; ++r) {
                float4 xi = __ldcs(xv);
                float4 o;
                o.x = fmaf(xi.x, wb0.x, wb0.y);
                o.y = fmaf(xi.y, wb1.x, wb1.y);
                o.z = fmaf(xi.z, wb2.x, wb2.y);
                o.w = fmaf(xi.w, wb3.x, wb3.y);
                __stcs(ov, o);
                xv += nv;
                ov += nv;
            }
        }
    }
}

extern "C" void kernel_launch(void* const* d_in, const int* in_sizes, int n_in,
                              void* d_out, int out_size)
{
    const float* x  = (const float*)d_in[0];   // (B, N) float32
    const float* kr = (const float*)d_in[1];   // (168, 1000) float32
    const float* br = (const float*)d_in[2];   // (168, 1000) float32
    float* out = (float*)d_out;

    const int N = 524288;
    const int B = in_sizes[0] / N;             // 64

    interleave_tab<<<(TABN + 255) / 256, 256>>>(kr, br);

    const int grid = N / (COLS * TILES);       // 1024 blocks
    bwl_prime_main<<<grid, TPB>>>(x, out, N, B);
}